// round 10
// baseline (speedup 1.0000x reference)
#include <cuda_runtime.h>
#include <cuda_bf16.h>

#define WARPS_PER_BLOCK 8
#define THREADS 256

typedef unsigned long long u64;

__host__ __device__ constexpr int msbbit(int v) { int b = 1; while (v >>= 1) b <<= 1; return b; }

__device__ __forceinline__ u64 pk(float lo, float hi) {
    u64 r; asm("mov.b64 %0, {%1, %2};" : "=l"(r) : "f"(lo), "f"(hi)); return r;
}
__device__ __forceinline__ void upk(u64 v, float& lo, float& hi) {
    asm("mov.b64 {%0, %1}, %2;" : "=f"(lo), "=f"(hi) : "l"(v));
}
__device__ __forceinline__ u64 swap64(u64 v) {
    u64 r;
    asm("{ .reg .b32 lo, hi; mov.b64 {lo, hi}, %1; mov.b64 %0, {hi, lo}; }"
        : "=l"(r) : "l"(v));
    return r;
}
__device__ __forceinline__ u64 fma2(u64 a, u64 b, u64 c) {
    u64 r; asm("fma.rn.f32x2 %0, %1, %2, %3;" : "=l"(r) : "l"(a), "l"(b), "l"(c)); return r;
}
__device__ __forceinline__ u64 mul2(u64 a, u64 b) {
    u64 r; asm("mul.rn.f32x2 %0, %1, %2;" : "=l"(r) : "l"(a), "l"(b)); return r;
}
__device__ __forceinline__ u64 neg64(u64 v) { return v ^ 0x8000000080000000ULL; }

__device__ __forceinline__ void cmul(float& ar, float& ai, float br, float bi) {
    float r = ar * br - ai * bi;
    float i = ar * bi + ai * br;
    ar = r; ai = i;
}

// Real Ry gate on logical bit p, in frame coordinates (lane 5b, reg 4b).
// MASK = coord pairing mask (low 4 = reg, high 5 = lane); ROLE = coord side mask.
// side0 row = (ct, -st), side1 row = (ct, +st). State packed over reg bit0 (j0).
template<int MASK, int ROLE>
__device__ __forceinline__ void gate_y(u64 (&RE)[8], u64 (&IM)[8],
                                       float ct, float st, int lane) {
    constexpr int ml = MASK & 0xF;
    constexpr int mw = (MASK >> 4) & 0x1F;
    constexpr int mh = ml >> 1;
    constexpr bool odd = (ml & 1) != 0;
    constexpr bool alt = (ROLE & 1) != 0;

    const int lp = __popc((ROLE >> 4) & lane) & 1;
    const float base = lp ? st : -st;          // partner coeff for reg-parity t=0
    const u64 C  = pk(ct, ct);
    const u64 SA = alt ? pk(base, -base) : pk(base, base);
    const u64 nSA = neg64(SA);

    if constexpr (mw == 0) {
        if constexpr (mh == 0) {
            #pragma unroll
            for (int h = 0; h < 8; ++h) {
                const bool T0 = (__popc(ROLE & (2 * h)) & 1) != 0;
                const u64 S = T0 ? nSA : SA;
                const u64 pre = swap64(RE[h]), pim = swap64(IM[h]);
                RE[h] = fma2(C, RE[h], mul2(S, pre));
                IM[h] = fma2(C, IM[h], mul2(S, pim));
            }
        } else {
            constexpr int hb = msbbit(mh);
            #pragma unroll
            for (int h = 0; h < 8; ++h) {
                if ((h & hb) != 0) continue;
                const int g = h ^ mh;
                const bool Th = (__popc(ROLE & (2 * h)) & 1) != 0;
                const bool Tg = (__popc(ROLE & (2 * g)) & 1) != 0;
                const u64 Sh = Th ? nSA : SA;
                const u64 Sg = Tg ? nSA : SA;
                u64 prh = RE[g], pih = IM[g], prg = RE[h], pig = IM[h];
                if constexpr (odd) { prh = swap64(prh); pih = swap64(pih);
                                     prg = swap64(prg); pig = swap64(pig); }
                const u64 nrh = fma2(C, RE[h], mul2(Sh, prh));
                const u64 nih = fma2(C, IM[h], mul2(Sh, pih));
                const u64 nrg = fma2(C, RE[g], mul2(Sg, prg));
                const u64 nig = fma2(C, IM[g], mul2(Sg, pig));
                RE[h] = nrh; IM[h] = nih; RE[g] = nrg; IM[g] = nig;
            }
        }
    } else {
        if constexpr (mh == 0) {
            #pragma unroll
            for (int h = 0; h < 8; ++h) {
                u64 pre = __shfl_xor_sync(0xffffffffu, RE[h], mw);
                u64 pim = __shfl_xor_sync(0xffffffffu, IM[h], mw);
                if constexpr (odd) { pre = swap64(pre); pim = swap64(pim); }
                const bool T0 = (__popc(ROLE & (2 * h)) & 1) != 0;
                const u64 S = T0 ? nSA : SA;
                RE[h] = fma2(C, RE[h], mul2(S, pre));
                IM[h] = fma2(C, IM[h], mul2(S, pim));
            }
        } else {
            constexpr int hb = msbbit(mh);
            #pragma unroll
            for (int h = 0; h < 8; ++h) {
                if ((h & hb) != 0) continue;
                const int g = h ^ mh;
                const bool Th = (__popc(ROLE & (2 * h)) & 1) != 0;
                const bool Tg = (__popc(ROLE & (2 * g)) & 1) != 0;
                const u64 Sh = Th ? nSA : SA;
                const u64 Sg = Tg ? nSA : SA;
                u64 prh = __shfl_xor_sync(0xffffffffu, RE[g], mw);
                u64 pih = __shfl_xor_sync(0xffffffffu, IM[g], mw);
                u64 prg = __shfl_xor_sync(0xffffffffu, RE[h], mw);
                u64 pig = __shfl_xor_sync(0xffffffffu, IM[h], mw);
                if constexpr (odd) { prh = swap64(prh); pih = swap64(pih);
                                     prg = swap64(prg); pig = swap64(pig); }
                const u64 nrh = fma2(C, RE[h], mul2(Sh, prh));
                const u64 nih = fma2(C, IM[h], mul2(Sh, pih));
                const u64 nrg = fma2(C, RE[g], mul2(Sg, prg));
                const u64 nig = fma2(C, IM[g], mul2(Sg, pig));
                RE[h] = nrh; IM[h] = nih; RE[g] = nrg; IM[g] = nig;
            }
        }
    }
}

// state *= precomputed unit-modulus diagonal (packed), DR/DI indexed [h][lane]
__device__ __forceinline__ void apply_diag(u64 (&RE)[8], u64 (&IM)[8],
                                           const u64 (*__restrict__ DR)[32],
                                           const u64 (*__restrict__ DI)[32], int lane) {
    #pragma unroll
    for (int h = 0; h < 8; ++h) {
        const u64 dr = DR[h][lane], di = DI[h][lane];
        const u64 nre = fma2(IM[h], neg64(di), mul2(RE[h], dr));
        const u64 nim = fma2(IM[h], dr, mul2(RE[h], di));
        RE[h] = nre; IM[h] = nim;
    }
}

__device__ __forceinline__ float laneWHT(float v, unsigned s0, unsigned s1, unsigned s2,
                                         unsigned s3, unsigned s4) {
    float t;
    t = __shfl_xor_sync(0xffffffffu, v, 1);  v = t + __uint_as_float(__float_as_uint(v) ^ s0);
    t = __shfl_xor_sync(0xffffffffu, v, 2);  v = t + __uint_as_float(__float_as_uint(v) ^ s1);
    t = __shfl_xor_sync(0xffffffffu, v, 4);  v = t + __uint_as_float(__float_as_uint(v) ^ s2);
    t = __shfl_xor_sync(0xffffffffu, v, 8);  v = t + __uint_as_float(__float_as_uint(v) ^ s3);
    t = __shfl_xor_sync(0xffffffffu, v, 16); v = t + __uint_as_float(__float_as_uint(v) ^ s4);
    return v;
}

// Frame: slot s = j0*0x003 ^ j1*0x006 ^ j2*0x00C ^ j3*0x018
//              ^ l0*0x001 ^ l1*0x020 ^ l2*0x040 ^ l3*0x080 ^ l4*0x100
__device__ __forceinline__ int slot_of(int ln, int j) {
    int s = 0;
    if (j & 1)  s ^= 0x003;
    if (j & 2)  s ^= 0x006;
    if (j & 4)  s ^= 0x00C;
    if (j & 8)  s ^= 0x018;
    if (ln & 1)  s ^= 0x001;
    if (ln & 2)  s ^= 0x020;
    if (ln & 4)  s ^= 0x040;
    if (ln & 8)  s ^= 0x080;
    if (ln & 16) s ^= 0x100;
    return s;
}

__global__ void __launch_bounds__(THREADS, 4)
qlayer_kernel(const float* __restrict__ x, const float* __restrict__ wts,
              float* __restrict__ out, int nsamp) {
    __shared__ float sw[81];
    __shared__ __align__(16) float s_m0[9][4];  // layer-0 matrices {m00r,m00i,m01r,m01i}
    __shared__ float s_y[2][9][2];              // layers 1,2 Ry coeffs {ct, st}
    __shared__ u64 sDR[2][8][32];               // diagonals D_A, D_B (cos), packed over j0
    __shared__ u64 sDI[2][8][32];               //                      (sin)

    const int tid = threadIdx.x;
    if (tid < 81) sw[tid] = wts[tid];
    __syncthreads();

    if (tid < 9) {
        const int qb = tid;
        const float phi = sw[qb * 3 + 0];
        const float th  = sw[qb * 3 + 1];
        const float om  = sw[qb * 3 + 2];
        float st, ct; sincosf(0.5f * th, &st, &ct);
        float sA, cA; sincosf(0.5f * (phi + om), &sA, &cA);
        float sB, cB; sincosf(0.5f * (phi - om), &sB, &cB);
        s_m0[qb][0] =  cA * ct;
        s_m0[qb][1] = -sA * ct;
        s_m0[qb][2] = -cB * st;
        s_m0[qb][3] = -sB * st;
    }
    if (tid < 18) {
        const int l = tid / 9 + 1, qb = tid % 9;
        float st, ct; sincosf(0.5f * sw[(l * 9 + qb) * 3 + 1], &st, &ct);
        s_y[l - 1][qb][0] = ct;
        s_y[l - 1][qb][1] = st;
    }
    {
        // D_A = Z(phi1)^{P1}; D_B = Z(om1)^{P1} * Z(phi2)^{P2}.
        // slot side1 (parity(row&s)=1) -> e^{+i a/2}, side0 -> e^{-i a/2}. (physical rows)
        constexpr int R1[9] = {0x1FF,0x1FE,0x1FC,0x1F8,0x1F0,0x1E0,0x1C0,0x180,0x0FF};
        constexpr int R2[9] = {0x0CC,0x066,0x133,0x198,0x0CF,0x060,0x13F,0x14C,0x099};
        const int h = tid >> 5, ln = tid & 31;
        const int sj[2] = { slot_of(ln, 2 * h), slot_of(ln, 2 * h + 1) };
        float thA[2] = {0.f, 0.f}, thB[2] = {0.f, 0.f};
        #pragma unroll
        for (int p = 0; p < 9; ++p) {
            const int q = 8 - p;
            const float f1 = sw[(9 + q) * 3 + 0];    // phi, layer 1
            const float o1 = sw[(9 + q) * 3 + 2];    // omega, layer 1
            const float f2 = sw[(18 + q) * 3 + 0];   // phi, layer 2
            #pragma unroll
            for (int e = 0; e < 2; ++e) {
                const int s = sj[e];
                const float g1 = (__popc(R1[p] & s) & 1) ? 0.5f : -0.5f;
                const float g2 = (__popc(R2[p] & s) & 1) ? 0.5f : -0.5f;
                thA[e] += g1 * f1;
                thB[e] += g1 * o1 + g2 * f2;
            }
        }
        float ca0, sa0, ca1, sa1, cb0, sb0, cb1, sb1;
        sincosf(thA[0], &sa0, &ca0); sincosf(thA[1], &sa1, &ca1);
        sincosf(thB[0], &sb0, &cb0); sincosf(thB[1], &sb1, &cb1);
        sDR[0][h][ln] = pk(ca0, ca1); sDI[0][h][ln] = pk(sa0, sa1);
        sDR[1][h][ln] = pk(cb0, cb1); sDI[1][h][ln] = pk(sb0, sb1);
    }
    __syncthreads();

    const int lane = tid & 31;
    const int warp = tid >> 5;
    const int b = blockIdx.x * WARPS_PER_BLOCK + warp;
    if (b >= nsamp) return;

    // --- per-qubit initial 2-vectors (every thread computes all 9; no broadcasts) ---
    float v0r[9], v0i[9], v1r[9], v1i[9];
    #pragma unroll
    for (int q = 0; q < 9; ++q) {
        const float xv = x[b * 9 + q];
        float sx, cx; sincosf(0.5f * xv, &sx, &cx);
        const float4 m = *reinterpret_cast<const float4*>(s_m0[q]);
        v0r[q] =  m.x * cx + m.w * sx;
        v0i[q] =  m.y * cx - m.z * sx;
        v1r[q] = -m.z * cx - m.y * sx;
        v1i[q] =  m.w * cx - m.x * sx;
    }
    const int l0 = lane & 1, l1 = (lane >> 1) & 1, l2 = (lane >> 2) & 1;
    const int l3 = (lane >> 3) & 1, l4 = (lane >> 4) & 1;

    // --- product state in frame coords ---
    // bit p factor: p0:w8[j0^l0] p1:w7[j0^j1] p2:w6[j1^j2] p3:w5[j2^j3] p4:w4[j3]
    //               p5:w3[l1] p6:w2[l2] p7:w1[l3] p8:w0[l4]   (w[q] = qubit q vector)
    float Br = l4 ? v1r[0] : v0r[0], Bi = l4 ? v1i[0] : v0i[0];
    cmul(Br, Bi, l3 ? v1r[1] : v0r[1], l3 ? v1i[1] : v0i[1]);
    cmul(Br, Bi, l2 ? v1r[2] : v0r[2], l2 ? v1i[2] : v0i[2]);
    cmul(Br, Bi, l1 ? v1r[3] : v0r[3], l1 ? v1i[3] : v0i[3]);

    u64 RE[8], IM[8];
    {
        float t1r[2], t1i[2];
        #pragma unroll
        for (int e3 = 0; e3 < 2; ++e3) {                 // j3
            t1r[e3] = Br; t1i[e3] = Bi;
            cmul(t1r[e3], t1i[e3], e3 ? v1r[4] : v0r[4], e3 ? v1i[4] : v0i[4]);
        }
        float t2r[4], t2i[4];
        #pragma unroll
        for (int t = 0; t < 4; ++t) {                    // (e2 = t&1, e3 = t>>1)
            const int e2 = t & 1, e3 = t >> 1;
            const int s3 = e2 ^ e3;
            t2r[t] = t1r[e3]; t2i[t] = t1i[e3];
            cmul(t2r[t], t2i[t], s3 ? v1r[5] : v0r[5], s3 ? v1i[5] : v0i[5]);
        }
        float t3r[8], t3i[8];
        #pragma unroll
        for (int h = 0; h < 8; ++h) {                    // h = j1 | j2<<1 | j3<<2
            const int e1 = h & 1, e2 = (h >> 1) & 1, e3 = h >> 2;
            const int s2 = e1 ^ e2;
            t3r[h] = t2r[e2 | (e3 << 1)]; t3i[h] = t2i[e2 | (e3 << 1)];
            cmul(t3r[h], t3i[h], s2 ? v1r[6] : v0r[6], s2 ? v1i[6] : v0i[6]);
        }
        // packed last two factors (over pack half = j0):
        const u64 W8R = pk(l0 ? v1r[8] : v0r[8], l0 ? v0r[8] : v1r[8]);
        const u64 W8I = pk(l0 ? v1i[8] : v0i[8], l0 ? v0i[8] : v1i[8]);
        const u64 W7R0 = pk(v0r[7], v1r[7]), W7I0 = pk(v0i[7], v1i[7]);
        const u64 W7R1 = pk(v1r[7], v0r[7]), W7I1 = pk(v1i[7], v0i[7]);
        #pragma unroll
        for (int h = 0; h < 8; ++h) {
            const u64 w7r = (h & 1) ? W7R1 : W7R0;
            const u64 w7i = (h & 1) ? W7I1 : W7I0;
            const u64 R0 = pk(t3r[h], t3r[h]);
            const u64 I0 = pk(t3i[h], t3i[h]);
            const u64 R1v = fma2(I0, neg64(w7i), mul2(R0, w7r));
            const u64 I1v = fma2(I0, w7r, mul2(R0, w7i));
            RE[h] = fma2(I1v, neg64(W8I), mul2(R1v, W8R));
            IM[h] = fma2(I1v, W8R, mul2(R1v, W8I));
        }
    }

    // --- D_A ---
    apply_diag(RE, IM, sDR[0], sDI[0], lane);

    // --- layer-1 Ry gates (frame coords; gate p -> qubit 8-p) ---
    gate_y<0x190, 0x1F0>(RE, IM, s_y[0][8][0], s_y[0][8][1], lane);  // p=0
    gate_y<0x001, 0x1E1>(RE, IM, s_y[0][7][0], s_y[0][7][1], lane);  // p=1
    gate_y<0x002, 0x1E2>(RE, IM, s_y[0][6][0], s_y[0][6][1], lane);  // p=2
    gate_y<0x004, 0x1E4>(RE, IM, s_y[0][5][0], s_y[0][5][1], lane);  // p=3
    gate_y<0x008, 0x1E8>(RE, IM, s_y[0][4][0], s_y[0][4][1], lane);  // p=4
    gate_y<0x03F, 0x1E0>(RE, IM, s_y[0][3][0], s_y[0][3][1], lane);  // p=5
    gate_y<0x060, 0x1C0>(RE, IM, s_y[0][2][0], s_y[0][2][1], lane);  // p=6
    gate_y<0x0C0, 0x180>(RE, IM, s_y[0][1][0], s_y[0][1][1], lane);  // p=7
    gate_y<0x180, 0x0F0>(RE, IM, s_y[0][0][0], s_y[0][0][1], lane);  // p=8

    // --- D_B ---
    apply_diag(RE, IM, sDR[1], sDI[1], lane);

    // --- layer-2 Ry gates ---  [Z(om2) dropped: pure phase before |.|^2]
    gate_y<0x16F, 0x0CA>(RE, IM, s_y[1][8][0], s_y[1][8][1], lane);  // p=0
    gate_y<0x1E1, 0x065>(RE, IM, s_y[1][7][0], s_y[1][7][1], lane);  // p=1
    gate_y<0x192, 0x13A>(RE, IM, s_y[1][6][0], s_y[1][6][1], lane);  // p=2
    gate_y<0x005, 0x184>(RE, IM, s_y[1][5][0], s_y[1][5][1], lane);  // p=3
    gate_y<0x00A, 0x0D8>(RE, IM, s_y[1][4][0], s_y[1][4][1], lane);  // p=4
    gate_y<0x03B, 0x060>(RE, IM, s_y[1][3][0], s_y[1][3][1], lane);  // p=5
    gate_y<0x068, 0x130>(RE, IM, s_y[1][2][0], s_y[1][2][1], lane);  // p=6
    gate_y<0x0FF, 0x14A>(RE, IM, s_y[1][1][0], s_y[1][1][1], lane);  // p=7
    gate_y<0x1E0, 0x095>(RE, IM, s_y[1][0][0], s_y[1][0][1], lane);  // p=8

    // --- probabilities, register-side WHT (over j) ---
    float prob[16];
    #pragma unroll
    for (int h = 0; h < 8; ++h) {
        const u64 P = fma2(IM[h], IM[h], mul2(RE[h], RE[h]));
        upk(P, prob[2 * h], prob[2 * h + 1]);
    }
    #pragma unroll
    for (int bb = 0; bb < 4; ++bb) {
        const int mk = 1 << bb;
        #pragma unroll
        for (int j = 0; j < 16; ++j) {
            if ((j & mk) != 0) continue;
            const float u = prob[j], v = prob[j | mk];
            prob[j] = u + v; prob[j | mk] = u - v;
        }
    }

    // --- lane-side WHTs; picks = M^T * ZM rows (coord Walsh indices) ---
    // w0:(A,0x15) w1:(D,0x0B) w2:(E,0x14) w3:(5,0x0F) w4:(2,0x19)
    // w5:(4,0x0B) w6:(F,0x1C) w7:(7,0x1F) w8:(E,0x07)
    const unsigned sg0 = (unsigned)( lane       & 1) << 31;
    const unsigned sg1 = (unsigned)((lane >> 1) & 1) << 31;
    const unsigned sg2 = (unsigned)((lane >> 2) & 1) << 31;
    const unsigned sg3 = (unsigned)((lane >> 3) & 1) << 31;
    const unsigned sg4 = (unsigned)((lane >> 4) & 1) << 31;
    const float SA = laneWHT(prob[0xA], sg0, sg1, sg2, sg3, sg4);
    const float SD = laneWHT(prob[0xD], sg0, sg1, sg2, sg3, sg4);
    const float SE = laneWHT(prob[0xE], sg0, sg1, sg2, sg3, sg4);
    const float S5 = laneWHT(prob[0x5], sg0, sg1, sg2, sg3, sg4);
    const float S2 = laneWHT(prob[0x2], sg0, sg1, sg2, sg3, sg4);
    const float S4 = laneWHT(prob[0x4], sg0, sg1, sg2, sg3, sg4);
    const float SF = laneWHT(prob[0xF], sg0, sg1, sg2, sg3, sg4);
    const float S7 = laneWHT(prob[0x7], sg0, sg1, sg2, sg3, sg4);

    const float r0 = __shfl_sync(0xffffffffu, SA, 0x15);
    const float r1 = __shfl_sync(0xffffffffu, SD, 0x0B);
    const float r2 = __shfl_sync(0xffffffffu, SE, 0x14);
    const float r3 = __shfl_sync(0xffffffffu, S5, 0x0F);
    const float r4 = __shfl_sync(0xffffffffu, S2, 0x19);
    const float r5 = __shfl_sync(0xffffffffu, S4, 0x0B);
    const float r6 = __shfl_sync(0xffffffffu, SF, 0x1C);
    const float r7 = __shfl_sync(0xffffffffu, S7, 0x1F);
    const float r8 = __shfl_sync(0xffffffffu, SE, 0x07);

    if (lane < 9) {
        float v = r0;
        if (lane == 1) v = r1;
        if (lane == 2) v = r2;
        if (lane == 3) v = r3;
        if (lane == 4) v = r4;
        if (lane == 5) v = r5;
        if (lane == 6) v = r6;
        if (lane == 7) v = r7;
        if (lane == 8) v = r8;
        out[b * 9 + lane] = v;
    }
}

extern "C" void kernel_launch(void* const* d_in, const int* in_sizes, int n_in,
                              void* d_out, int out_size) {
    const float* x   = (const float*)d_in[0];   // (32768, 9) float32
    const float* wts = (const float*)d_in[1];   // (3, 9, 3) float32
    float* out = (float*)d_out;                 // (32768, 9) float32
    const int nsamp = in_sizes[0] / 9;
    const int blocks = (nsamp + WARPS_PER_BLOCK - 1) / WARPS_PER_BLOCK;
    qlayer_kernel<<<blocks, THREADS>>>(x, wts, out, nsamp);
}

// round 11
// speedup vs baseline: 1.1438x; 1.1438x over previous
#include <cuda_runtime.h>
#include <cuda_bf16.h>

#define WARPS_PER_BLOCK 8
#define THREADS 256

typedef unsigned long long u64;

__host__ __device__ constexpr int msbbit(int v) { int b = 1; while (v >>= 1) b <<= 1; return b; }

__device__ __forceinline__ u64 pk(float lo, float hi) {
    u64 r; asm("mov.b64 %0, {%1, %2};" : "=l"(r) : "f"(lo), "f"(hi)); return r;
}
__device__ __forceinline__ void upk(u64 v, float& lo, float& hi) {
    asm("mov.b64 {%0, %1}, %2;" : "=f"(lo), "=f"(hi) : "l"(v));
}
__device__ __forceinline__ u64 swap64(u64 v) {
    u64 r;
    asm("{ .reg .b32 lo, hi; mov.b64 {lo, hi}, %1; mov.b64 %0, {hi, lo}; }"
        : "=l"(r) : "l"(v));
    return r;
}
__device__ __forceinline__ u64 fma2(u64 a, u64 b, u64 c) {
    u64 r; asm("fma.rn.f32x2 %0, %1, %2, %3;" : "=l"(r) : "l"(a), "l"(b), "l"(c)); return r;
}
__device__ __forceinline__ u64 mul2(u64 a, u64 b) {
    u64 r; asm("mul.rn.f32x2 %0, %1, %2;" : "=l"(r) : "l"(a), "l"(b)); return r;
}
__device__ __forceinline__ u64 neg64(u64 v) { return v ^ 0x8000000080000000ULL; }

__device__ __forceinline__ void cmul(float& ar, float& ai, float br, float bi) {
    float r = ar * br - ai * bi;
    float i = ar * bi + ai * br;
    ar = r; ai = i;
}

// Real Ry gate on logical bit p, in frame coordinates (lane 5b, reg 4b).
// MASK = coord pairing mask (low 4 = reg, high 5 = lane); ROLE = coord side mask.
// side0 row = (ct, -st), side1 row = (ct, +st). State packed over reg bit0 (j0).
template<int MASK, int ROLE>
__device__ __forceinline__ void gate_y(u64 (&RE)[8], u64 (&IM)[8],
                                       float ct, float st, int lane) {
    constexpr int ml = MASK & 0xF;
    constexpr int mw = (MASK >> 4) & 0x1F;
    constexpr int mh = ml >> 1;
    constexpr bool odd = (ml & 1) != 0;
    constexpr bool alt = (ROLE & 1) != 0;

    const int lp = __popc((ROLE >> 4) & lane) & 1;
    const float base = lp ? st : -st;          // partner coeff for reg-parity t=0
    const u64 C  = pk(ct, ct);
    const u64 SA = alt ? pk(base, -base) : pk(base, base);
    const u64 nSA = neg64(SA);

    if constexpr (mw == 0) {
        if constexpr (mh == 0) {
            #pragma unroll
            for (int h = 0; h < 8; ++h) {
                const bool T0 = (__popc(ROLE & (2 * h)) & 1) != 0;
                const u64 S = T0 ? nSA : SA;
                const u64 pre = swap64(RE[h]), pim = swap64(IM[h]);
                RE[h] = fma2(C, RE[h], mul2(S, pre));
                IM[h] = fma2(C, IM[h], mul2(S, pim));
            }
        } else {
            constexpr int hb = msbbit(mh);
            #pragma unroll
            for (int h = 0; h < 8; ++h) {
                if ((h & hb) != 0) continue;
                const int g = h ^ mh;
                const bool Th = (__popc(ROLE & (2 * h)) & 1) != 0;
                const bool Tg = (__popc(ROLE & (2 * g)) & 1) != 0;
                const u64 Sh = Th ? nSA : SA;
                const u64 Sg = Tg ? nSA : SA;
                u64 prh = RE[g], pih = IM[g], prg = RE[h], pig = IM[h];
                if constexpr (odd) { prh = swap64(prh); pih = swap64(pih);
                                     prg = swap64(prg); pig = swap64(pig); }
                const u64 nrh = fma2(C, RE[h], mul2(Sh, prh));
                const u64 nih = fma2(C, IM[h], mul2(Sh, pih));
                const u64 nrg = fma2(C, RE[g], mul2(Sg, prg));
                const u64 nig = fma2(C, IM[g], mul2(Sg, pig));
                RE[h] = nrh; IM[h] = nih; RE[g] = nrg; IM[g] = nig;
            }
        }
    } else {
        if constexpr (mh == 0) {
            #pragma unroll
            for (int h = 0; h < 8; ++h) {
                u64 pre = __shfl_xor_sync(0xffffffffu, RE[h], mw);
                u64 pim = __shfl_xor_sync(0xffffffffu, IM[h], mw);
                if constexpr (odd) { pre = swap64(pre); pim = swap64(pim); }
                const bool T0 = (__popc(ROLE & (2 * h)) & 1) != 0;
                const u64 S = T0 ? nSA : SA;
                RE[h] = fma2(C, RE[h], mul2(S, pre));
                IM[h] = fma2(C, IM[h], mul2(S, pim));
            }
        } else {
            constexpr int hb = msbbit(mh);
            #pragma unroll
            for (int h = 0; h < 8; ++h) {
                if ((h & hb) != 0) continue;
                const int g = h ^ mh;
                const bool Th = (__popc(ROLE & (2 * h)) & 1) != 0;
                const bool Tg = (__popc(ROLE & (2 * g)) & 1) != 0;
                const u64 Sh = Th ? nSA : SA;
                const u64 Sg = Tg ? nSA : SA;
                u64 prh = __shfl_xor_sync(0xffffffffu, RE[g], mw);
                u64 pih = __shfl_xor_sync(0xffffffffu, IM[g], mw);
                u64 prg = __shfl_xor_sync(0xffffffffu, RE[h], mw);
                u64 pig = __shfl_xor_sync(0xffffffffu, IM[h], mw);
                if constexpr (odd) { prh = swap64(prh); pih = swap64(pih);
                                     prg = swap64(prg); pig = swap64(pig); }
                const u64 nrh = fma2(C, RE[h], mul2(Sh, prh));
                const u64 nih = fma2(C, IM[h], mul2(Sh, pih));
                const u64 nrg = fma2(C, RE[g], mul2(Sg, prg));
                const u64 nig = fma2(C, IM[g], mul2(Sg, pig));
                RE[h] = nrh; IM[h] = nih; RE[g] = nrg; IM[g] = nig;
            }
        }
    }
}

// state *= precomputed unit-modulus diagonal (packed), DR/DI indexed [h][lane]
__device__ __forceinline__ void apply_diag(u64 (&RE)[8], u64 (&IM)[8],
                                           const u64 (*__restrict__ DR)[32],
                                           const u64 (*__restrict__ DI)[32], int lane) {
    #pragma unroll
    for (int h = 0; h < 8; ++h) {
        const u64 dr = DR[h][lane], di = DI[h][lane];
        const u64 nre = fma2(IM[h], neg64(di), mul2(RE[h], dr));
        const u64 nim = fma2(IM[h], dr, mul2(RE[h], di));
        RE[h] = nre; IM[h] = nim;
    }
}

__device__ __forceinline__ float laneWHT(float v, unsigned s0, unsigned s1, unsigned s2,
                                         unsigned s3, unsigned s4) {
    float t;
    t = __shfl_xor_sync(0xffffffffu, v, 1);  v = t + __uint_as_float(__float_as_uint(v) ^ s0);
    t = __shfl_xor_sync(0xffffffffu, v, 2);  v = t + __uint_as_float(__float_as_uint(v) ^ s1);
    t = __shfl_xor_sync(0xffffffffu, v, 4);  v = t + __uint_as_float(__float_as_uint(v) ^ s2);
    t = __shfl_xor_sync(0xffffffffu, v, 8);  v = t + __uint_as_float(__float_as_uint(v) ^ s3);
    t = __shfl_xor_sync(0xffffffffu, v, 16); v = t + __uint_as_float(__float_as_uint(v) ^ s4);
    return v;
}

// Frame: slot s = j0*0x003 ^ j1*0x006 ^ j2*0x00C ^ j3*0x018
//              ^ l0*0x001 ^ l1*0x020 ^ l2*0x040 ^ l3*0x080 ^ l4*0x100
__device__ __forceinline__ int slot_of(int ln, int j) {
    int s = 0;
    if (j & 1)  s ^= 0x003;
    if (j & 2)  s ^= 0x006;
    if (j & 4)  s ^= 0x00C;
    if (j & 8)  s ^= 0x018;
    if (ln & 1)  s ^= 0x001;
    if (ln & 2)  s ^= 0x020;
    if (ln & 4)  s ^= 0x040;
    if (ln & 8)  s ^= 0x080;
    if (ln & 16) s ^= 0x100;
    return s;
}

__global__ void __launch_bounds__(THREADS, 4)
qlayer_kernel(const float* __restrict__ x, const float* __restrict__ wts,
              float* __restrict__ out, int nsamp) {
    __shared__ float sw[81];
    __shared__ __align__(16) float s_m0[9][4];  // layer-0 matrices {m00r,m00i,m01r,m01i}
    __shared__ float s_y[2][9][2];              // layers 1,2 Ry coeffs {ct, st}
    __shared__ u64 sDR[2][8][32];               // diagonals D_A, D_B (cos), packed over j0
    __shared__ u64 sDI[2][8][32];               //                      (sin)

    const int tid = threadIdx.x;
    if (tid < 81) sw[tid] = wts[tid];
    __syncthreads();

    if (tid < 9) {
        const int qb = tid;
        const float phi = sw[qb * 3 + 0];
        const float th  = sw[qb * 3 + 1];
        const float om  = sw[qb * 3 + 2];
        float st, ct; sincosf(0.5f * th, &st, &ct);
        float sA, cA; sincosf(0.5f * (phi + om), &sA, &cA);
        float sB, cB; sincosf(0.5f * (phi - om), &sB, &cB);
        s_m0[qb][0] =  cA * ct;
        s_m0[qb][1] = -sA * ct;
        s_m0[qb][2] = -cB * st;
        s_m0[qb][3] = -sB * st;
    }
    if (tid < 18) {
        const int l = tid / 9 + 1, qb = tid % 9;
        float st, ct; sincosf(0.5f * sw[(l * 9 + qb) * 3 + 1], &st, &ct);
        s_y[l - 1][qb][0] = ct;
        s_y[l - 1][qb][1] = st;
    }
    {
        // D_A = Z(phi1)^{P1}; D_B = Z(om1)^{P1} * Z(phi2)^{P2}.
        // slot side1 (parity(row&s)=1) -> e^{+i a/2}, side0 -> e^{-i a/2}. (physical rows)
        constexpr int R1[9] = {0x1FF,0x1FE,0x1FC,0x1F8,0x1F0,0x1E0,0x1C0,0x180,0x0FF};
        constexpr int R2[9] = {0x0CC,0x066,0x133,0x198,0x0CF,0x060,0x13F,0x14C,0x099};
        const int h = tid >> 5, ln = tid & 31;
        const int sj[2] = { slot_of(ln, 2 * h), slot_of(ln, 2 * h + 1) };
        float thA[2] = {0.f, 0.f}, thB[2] = {0.f, 0.f};
        #pragma unroll
        for (int p = 0; p < 9; ++p) {
            const int q = 8 - p;
            const float f1 = sw[(9 + q) * 3 + 0];    // phi, layer 1
            const float o1 = sw[(9 + q) * 3 + 2];    // omega, layer 1
            const float f2 = sw[(18 + q) * 3 + 0];   // phi, layer 2
            #pragma unroll
            for (int e = 0; e < 2; ++e) {
                const int s = sj[e];
                const float g1 = (__popc(R1[p] & s) & 1) ? 0.5f : -0.5f;
                const float g2 = (__popc(R2[p] & s) & 1) ? 0.5f : -0.5f;
                thA[e] += g1 * f1;
                thB[e] += g1 * o1 + g2 * f2;
            }
        }
        float ca0, sa0, ca1, sa1, cb0, sb0, cb1, sb1;
        sincosf(thA[0], &sa0, &ca0); sincosf(thA[1], &sa1, &ca1);
        sincosf(thB[0], &sb0, &cb0); sincosf(thB[1], &sb1, &cb1);
        sDR[0][h][ln] = pk(ca0, ca1); sDI[0][h][ln] = pk(sa0, sa1);
        sDR[1][h][ln] = pk(cb0, cb1); sDI[1][h][ln] = pk(sb0, sb1);
    }
    __syncthreads();

    const int lane = tid & 31;
    const int warp = tid >> 5;
    const int b = blockIdx.x * WARPS_PER_BLOCK + warp;
    if (b >= nsamp) return;

    // --- per-qubit initial 2-vectors: lanes 0-8 compute, then broadcast ---
    float v0r = 0.f, v0i = 0.f, v1r = 0.f, v1i = 0.f;
    if (lane < 9) {
        const float xv = x[b * 9 + lane];
        float sx, cx; sincosf(0.5f * xv, &sx, &cx);
        const float4 m = *reinterpret_cast<const float4*>(s_m0[lane]);
        v0r =  m.x * cx + m.w * sx;
        v0i =  m.y * cx - m.z * sx;
        v1r = -m.z * cx - m.y * sx;
        v1i =  m.w * cx - m.x * sx;
    }
    float w0r[9], w0i[9], w1r[9], w1i[9];
    #pragma unroll
    for (int q = 0; q < 9; ++q) {
        w0r[q] = __shfl_sync(0xffffffffu, v0r, q);
        w0i[q] = __shfl_sync(0xffffffffu, v0i, q);
        w1r[q] = __shfl_sync(0xffffffffu, v1r, q);
        w1i[q] = __shfl_sync(0xffffffffu, v1i, q);
    }

    const int l0 = lane & 1, l1 = (lane >> 1) & 1, l2 = (lane >> 2) & 1;
    const int l3 = (lane >> 3) & 1, l4 = (lane >> 4) & 1;

    // --- product state in frame coords ---
    // bit p factor: p0:w8[j0^l0] p1:w7[j0^j1] p2:w6[j1^j2] p3:w5[j2^j3] p4:w4[j3]
    //               p5:w3[l1] p6:w2[l2] p7:w1[l3] p8:w0[l4]   (w[q] = qubit q vector)
    float Br = l4 ? w1r[0] : w0r[0], Bi = l4 ? w1i[0] : w0i[0];
    cmul(Br, Bi, l3 ? w1r[1] : w0r[1], l3 ? w1i[1] : w0i[1]);
    cmul(Br, Bi, l2 ? w1r[2] : w0r[2], l2 ? w1i[2] : w0i[2]);
    cmul(Br, Bi, l1 ? w1r[3] : w0r[3], l1 ? w1i[3] : w0i[3]);

    u64 RE[8], IM[8];
    {
        float t1r[2], t1i[2];
        #pragma unroll
        for (int e3 = 0; e3 < 2; ++e3) {                 // j3
            t1r[e3] = Br; t1i[e3] = Bi;
            cmul(t1r[e3], t1i[e3], e3 ? w1r[4] : w0r[4], e3 ? w1i[4] : w0i[4]);
        }
        float t2r[4], t2i[4];
        #pragma unroll
        for (int t = 0; t < 4; ++t) {                    // (e2 = t&1, e3 = t>>1)
            const int e2 = t & 1, e3 = t >> 1;
            const int s3 = e2 ^ e3;
            t2r[t] = t1r[e3]; t2i[t] = t1i[e3];
            cmul(t2r[t], t2i[t], s3 ? w1r[5] : w0r[5], s3 ? w1i[5] : w0i[5]);
        }
        float t3r[8], t3i[8];
        #pragma unroll
        for (int h = 0; h < 8; ++h) {                    // h = j1 | j2<<1 | j3<<2
            const int e1 = h & 1, e2 = (h >> 1) & 1, e3 = h >> 2;
            const int s2 = e1 ^ e2;
            t3r[h] = t2r[e2 | (e3 << 1)]; t3i[h] = t2i[e2 | (e3 << 1)];
            cmul(t3r[h], t3i[h], s2 ? w1r[6] : w0r[6], s2 ? w1i[6] : w0i[6]);
        }
        // packed last two factors (over pack half = j0):
        const u64 W8R = pk(l0 ? w1r[8] : w0r[8], l0 ? w0r[8] : w1r[8]);
        const u64 W8I = pk(l0 ? w1i[8] : w0i[8], l0 ? w0i[8] : w1i[8]);
        const u64 W7R0 = pk(w0r[7], w1r[7]), W7I0 = pk(w0i[7], w1i[7]);
        const u64 W7R1 = pk(w1r[7], w0r[7]), W7I1 = pk(w1i[7], w0i[7]);
        #pragma unroll
        for (int h = 0; h < 8; ++h) {
            const u64 w7r = (h & 1) ? W7R1 : W7R0;
            const u64 w7i = (h & 1) ? W7I1 : W7I0;
            const u64 R0 = pk(t3r[h], t3r[h]);
            const u64 I0 = pk(t3i[h], t3i[h]);
            const u64 R1v = fma2(I0, neg64(w7i), mul2(R0, w7r));
            const u64 I1v = fma2(I0, w7r, mul2(R0, w7i));
            RE[h] = fma2(I1v, neg64(W8I), mul2(R1v, W8R));
            IM[h] = fma2(I1v, W8R, mul2(R1v, W8I));
        }
    }

    // --- D_A ---
    apply_diag(RE, IM, sDR[0], sDI[0], lane);

    // --- layer-1 Ry gates (frame coords; gate p -> qubit 8-p) ---
    gate_y<0x190, 0x1F0>(RE, IM, s_y[0][8][0], s_y[0][8][1], lane);  // p=0
    gate_y<0x001, 0x1E1>(RE, IM, s_y[0][7][0], s_y[0][7][1], lane);  // p=1
    gate_y<0x002, 0x1E2>(RE, IM, s_y[0][6][0], s_y[0][6][1], lane);  // p=2
    gate_y<0x004, 0x1E4>(RE, IM, s_y[0][5][0], s_y[0][5][1], lane);  // p=3
    gate_y<0x008, 0x1E8>(RE, IM, s_y[0][4][0], s_y[0][4][1], lane);  // p=4
    gate_y<0x03F, 0x1E0>(RE, IM, s_y[0][3][0], s_y[0][3][1], lane);  // p=5
    gate_y<0x060, 0x1C0>(RE, IM, s_y[0][2][0], s_y[0][2][1], lane);  // p=6
    gate_y<0x0C0, 0x180>(RE, IM, s_y[0][1][0], s_y[0][1][1], lane);  // p=7
    gate_y<0x180, 0x0F0>(RE, IM, s_y[0][0][0], s_y[0][0][1], lane);  // p=8

    // --- D_B ---
    apply_diag(RE, IM, sDR[1], sDI[1], lane);

    // --- layer-2 Ry gates ---  [Z(om2) dropped: pure phase before |.|^2]
    gate_y<0x16F, 0x0CA>(RE, IM, s_y[1][8][0], s_y[1][8][1], lane);  // p=0
    gate_y<0x1E1, 0x065>(RE, IM, s_y[1][7][0], s_y[1][7][1], lane);  // p=1
    gate_y<0x192, 0x13A>(RE, IM, s_y[1][6][0], s_y[1][6][1], lane);  // p=2
    gate_y<0x005, 0x184>(RE, IM, s_y[1][5][0], s_y[1][5][1], lane);  // p=3
    gate_y<0x00A, 0x0D8>(RE, IM, s_y[1][4][0], s_y[1][4][1], lane);  // p=4
    gate_y<0x03B, 0x060>(RE, IM, s_y[1][3][0], s_y[1][3][1], lane);  // p=5
    gate_y<0x068, 0x130>(RE, IM, s_y[1][2][0], s_y[1][2][1], lane);  // p=6
    gate_y<0x0FF, 0x14A>(RE, IM, s_y[1][1][0], s_y[1][1][1], lane);  // p=7
    gate_y<0x1E0, 0x095>(RE, IM, s_y[1][0][0], s_y[1][0][1], lane);  // p=8

    // --- probabilities, register-side WHT (over j) ---
    float prob[16];
    #pragma unroll
    for (int h = 0; h < 8; ++h) {
        const u64 P = fma2(IM[h], IM[h], mul2(RE[h], RE[h]));
        upk(P, prob[2 * h], prob[2 * h + 1]);
    }
    #pragma unroll
    for (int bb = 0; bb < 4; ++bb) {
        const int mk = 1 << bb;
        #pragma unroll
        for (int j = 0; j < 16; ++j) {
            if ((j & mk) != 0) continue;
            const float u = prob[j], v = prob[j | mk];
            prob[j] = u + v; prob[j | mk] = u - v;
        }
    }

    // --- lane-side WHTs; picks = M^T * ZM rows (coord Walsh indices) ---
    // w0:(A,0x15) w1:(D,0x0B) w2:(E,0x14) w3:(5,0x0F) w4:(2,0x19)
    // w5:(4,0x0B) w6:(F,0x1C) w7:(7,0x1F) w8:(E,0x07)
    const unsigned sg0 = (unsigned)( lane       & 1) << 31;
    const unsigned sg1 = (unsigned)((lane >> 1) & 1) << 31;
    const unsigned sg2 = (unsigned)((lane >> 2) & 1) << 31;
    const unsigned sg3 = (unsigned)((lane >> 3) & 1) << 31;
    const unsigned sg4 = (unsigned)((lane >> 4) & 1) << 31;
    const float SA = laneWHT(prob[0xA], sg0, sg1, sg2, sg3, sg4);
    const float SD = laneWHT(prob[0xD], sg0, sg1, sg2, sg3, sg4);
    const float SE = laneWHT(prob[0xE], sg0, sg1, sg2, sg3, sg4);
    const float S5 = laneWHT(prob[0x5], sg0, sg1, sg2, sg3, sg4);
    const float S2 = laneWHT(prob[0x2], sg0, sg1, sg2, sg3, sg4);
    const float S4 = laneWHT(prob[0x4], sg0, sg1, sg2, sg3, sg4);
    const float SF = laneWHT(prob[0xF], sg0, sg1, sg2, sg3, sg4);
    const float S7 = laneWHT(prob[0x7], sg0, sg1, sg2, sg3, sg4);

    const float r0 = __shfl_sync(0xffffffffu, SA, 0x15);
    const float r1 = __shfl_sync(0xffffffffu, SD, 0x0B);
    const float r2 = __shfl_sync(0xffffffffu, SE, 0x14);
    const float r3 = __shfl_sync(0xffffffffu, S5, 0x0F);
    const float r4 = __shfl_sync(0xffffffffu, S2, 0x19);
    const float r5 = __shfl_sync(0xffffffffu, S4, 0x0B);
    const float r6 = __shfl_sync(0xffffffffu, SF, 0x1C);
    const float r7 = __shfl_sync(0xffffffffu, S7, 0x1F);
    const float r8 = __shfl_sync(0xffffffffu, SE, 0x07);

    if (lane < 9) {
        float v = r0;
        if (lane == 1) v = r1;
        if (lane == 2) v = r2;
        if (lane == 3) v = r3;
        if (lane == 4) v = r4;
        if (lane == 5) v = r5;
        if (lane == 6) v = r6;
        if (lane == 7) v = r7;
        if (lane == 8) v = r8;
        out[b * 9 + lane] = v;
    }
}

extern "C" void kernel_launch(void* const* d_in, const int* in_sizes, int n_in,
                              void* d_out, int out_size) {
    const float* x   = (const float*)d_in[0];   // (32768, 9) float32
    const float* wts = (const float*)d_in[1];   // (3, 9, 3) float32
    float* out = (float*)d_out;                 // (32768, 9) float32
    const int nsamp = in_sizes[0] / 9;
    const int blocks = (nsamp + WARPS_PER_BLOCK - 1) / WARPS_PER_BLOCK;
    qlayer_kernel<<<blocks, THREADS>>>(x, wts, out, nsamp);
}

// round 12
// speedup vs baseline: 1.1487x; 1.0043x over previous
#include <cuda_runtime.h>
#include <cuda_bf16.h>

#define WARPS_PER_BLOCK 8
#define THREADS 256

typedef unsigned long long u64;

__host__ __device__ constexpr int msbbit(int v) { int b = 1; while (v >>= 1) b <<= 1; return b; }

__device__ __forceinline__ u64 pk(float lo, float hi) {
    u64 r; asm("mov.b64 %0, {%1, %2};" : "=l"(r) : "f"(lo), "f"(hi)); return r;
}
__device__ __forceinline__ void upk(u64 v, float& lo, float& hi) {
    asm("mov.b64 {%0, %1}, %2;" : "=f"(lo), "=f"(hi) : "l"(v));
}
__device__ __forceinline__ u64 swap64(u64 v) {
    u64 r;
    asm("{ .reg .b32 lo, hi; mov.b64 {lo, hi}, %1; mov.b64 %0, {hi, lo}; }"
        : "=l"(r) : "l"(v));
    return r;
}
__device__ __forceinline__ u64 fma2(u64 a, u64 b, u64 c) {
    u64 r; asm("fma.rn.f32x2 %0, %1, %2, %3;" : "=l"(r) : "l"(a), "l"(b), "l"(c)); return r;
}
__device__ __forceinline__ u64 mul2(u64 a, u64 b) {
    u64 r; asm("mul.rn.f32x2 %0, %1, %2;" : "=l"(r) : "l"(a), "l"(b)); return r;
}
__device__ __forceinline__ u64 neg64(u64 v) { return v ^ 0x8000000080000000ULL; }

__device__ __forceinline__ void cmul(float& ar, float& ai, float br, float bi) {
    float r = ar * br - ai * bi;
    float i = ar * bi + ai * br;
    ar = r; ai = i;
}

// Real Ry gate on logical bit p, in frame coordinates (lane 5b, reg 4b).
// MASK = coord pairing mask (low 4 = reg, high 5 = lane); ROLE = coord side mask.
// side0 row = (ct, -st), side1 row = (ct, +st). State packed over reg bit0 (j0).
template<int MASK, int ROLE>
__device__ __forceinline__ void gate_y(u64 (&RE)[8], u64 (&IM)[8],
                                       float ct, float st, int lane) {
    constexpr int ml = MASK & 0xF;
    constexpr int mw = (MASK >> 4) & 0x1F;
    constexpr int mh = ml >> 1;
    constexpr bool odd = (ml & 1) != 0;
    constexpr bool alt = (ROLE & 1) != 0;

    const int lp = __popc((ROLE >> 4) & lane) & 1;
    const float base = lp ? st : -st;          // partner coeff for reg-parity t=0
    const u64 C  = pk(ct, ct);
    const u64 SA = alt ? pk(base, -base) : pk(base, base);
    const u64 nSA = neg64(SA);

    if constexpr (mw == 0) {
        if constexpr (mh == 0) {
            #pragma unroll
            for (int h = 0; h < 8; ++h) {
                const bool T0 = (__popc(ROLE & (2 * h)) & 1) != 0;
                const u64 S = T0 ? nSA : SA;
                const u64 pre = swap64(RE[h]), pim = swap64(IM[h]);
                RE[h] = fma2(C, RE[h], mul2(S, pre));
                IM[h] = fma2(C, IM[h], mul2(S, pim));
            }
        } else {
            constexpr int hb = msbbit(mh);
            #pragma unroll
            for (int h = 0; h < 8; ++h) {
                if ((h & hb) != 0) continue;
                const int g = h ^ mh;
                const bool Th = (__popc(ROLE & (2 * h)) & 1) != 0;
                const bool Tg = (__popc(ROLE & (2 * g)) & 1) != 0;
                const u64 Sh = Th ? nSA : SA;
                const u64 Sg = Tg ? nSA : SA;
                u64 prh = RE[g], pih = IM[g], prg = RE[h], pig = IM[h];
                if constexpr (odd) { prh = swap64(prh); pih = swap64(pih);
                                     prg = swap64(prg); pig = swap64(pig); }
                const u64 nrh = fma2(C, RE[h], mul2(Sh, prh));
                const u64 nih = fma2(C, IM[h], mul2(Sh, pih));
                const u64 nrg = fma2(C, RE[g], mul2(Sg, prg));
                const u64 nig = fma2(C, IM[g], mul2(Sg, pig));
                RE[h] = nrh; IM[h] = nih; RE[g] = nrg; IM[g] = nig;
            }
        }
    } else {
        if constexpr (mh == 0) {
            #pragma unroll
            for (int h = 0; h < 8; ++h) {
                u64 pre = __shfl_xor_sync(0xffffffffu, RE[h], mw);
                u64 pim = __shfl_xor_sync(0xffffffffu, IM[h], mw);
                if constexpr (odd) { pre = swap64(pre); pim = swap64(pim); }
                const bool T0 = (__popc(ROLE & (2 * h)) & 1) != 0;
                const u64 S = T0 ? nSA : SA;
                RE[h] = fma2(C, RE[h], mul2(S, pre));
                IM[h] = fma2(C, IM[h], mul2(S, pim));
            }
        } else {
            constexpr int hb = msbbit(mh);
            #pragma unroll
            for (int h = 0; h < 8; ++h) {
                if ((h & hb) != 0) continue;
                const int g = h ^ mh;
                const bool Th = (__popc(ROLE & (2 * h)) & 1) != 0;
                const bool Tg = (__popc(ROLE & (2 * g)) & 1) != 0;
                const u64 Sh = Th ? nSA : SA;
                const u64 Sg = Tg ? nSA : SA;
                u64 prh = __shfl_xor_sync(0xffffffffu, RE[g], mw);
                u64 pih = __shfl_xor_sync(0xffffffffu, IM[g], mw);
                u64 prg = __shfl_xor_sync(0xffffffffu, RE[h], mw);
                u64 pig = __shfl_xor_sync(0xffffffffu, IM[h], mw);
                if constexpr (odd) { prh = swap64(prh); pih = swap64(pih);
                                     prg = swap64(prg); pig = swap64(pig); }
                const u64 nrh = fma2(C, RE[h], mul2(Sh, prh));
                const u64 nih = fma2(C, IM[h], mul2(Sh, pih));
                const u64 nrg = fma2(C, RE[g], mul2(Sg, prg));
                const u64 nig = fma2(C, IM[g], mul2(Sg, pig));
                RE[h] = nrh; IM[h] = nih; RE[g] = nrg; IM[g] = nig;
            }
        }
    }
}

// Fused pair of commuting L2 Ry gates sharing lane mask 0x1E:
//   A = (MASK 0x1E1, ROLE 0x065), B = (MASK 0x1E0, ROLE 0x095).
// out(u) = cAcB in(u) + cB sA(u) in(u^0x1E1) + cA sB(u) in(u^0x1E0)
//        + stA stB sgnAB(lane) in(u^0x001)
// sgnAB depends only on lane (ROLE_A^ROLE_B = 0x0F0); both reg-roles = 5 -> same
// per-pack alternation pattern T(h) = bit1(h) and element alternation on j0.
__device__ __forceinline__ void gate_fused_1E(u64 (&RE)[8], u64 (&IM)[8],
                                              float cA, float stA, float cB, float stB,
                                              int lane) {
    const int lpA  = __popc(0x06 & lane) & 1;
    const int lpB  = __popc(0x09 & lane) & 1;
    const int lpAB = __popc(0x0F & lane) & 1;
    const float cc    = cA * cB;
    const float baseA = (lpA ? stA : -stA) * cB;
    const float baseB = (lpB ? stB : -stB) * cA;
    const float baseAB = lpAB ? -(stA * stB) : (stA * stB);

    const u64 KC  = pk(cc, cc);
    const u64 KA  = pk(baseA, -baseA);   // reg-role bit0 = 1: element alternation
    const u64 nKA = neg64(KA);
    const u64 KB  = pk(baseB, -baseB);
    const u64 nKB = neg64(KB);
    const u64 KAB = pk(baseAB, baseAB);  // reg-role 0: constant within pack

    #pragma unroll
    for (int h = 0; h < 8; ++h) {
        const bool T = ((h >> 1) & 1) != 0;   // popc(5 & 2h) & 1
        const u64 SApk = T ? nKA : KA;
        const u64 SBpk = T ? nKB : KB;
        const u64 pre = __shfl_xor_sync(0xffffffffu, RE[h], 0x1E);
        const u64 pim = __shfl_xor_sync(0xffffffffu, IM[h], 0x1E);
        const u64 nr = fma2(KC, RE[h], fma2(SApk, swap64(pre),
                        fma2(SBpk, pre, mul2(KAB, swap64(RE[h])))));
        const u64 ni = fma2(KC, IM[h], fma2(SApk, swap64(pim),
                        fma2(SBpk, pim, mul2(KAB, swap64(IM[h])))));
        RE[h] = nr; IM[h] = ni;
    }
}

// state *= precomputed unit-modulus diagonal (packed), DR/DI indexed [h][lane]
__device__ __forceinline__ void apply_diag(u64 (&RE)[8], u64 (&IM)[8],
                                           const u64 (*__restrict__ DR)[32],
                                           const u64 (*__restrict__ DI)[32], int lane) {
    #pragma unroll
    for (int h = 0; h < 8; ++h) {
        const u64 dr = DR[h][lane], di = DI[h][lane];
        const u64 nre = fma2(IM[h], neg64(di), mul2(RE[h], dr));
        const u64 nim = fma2(IM[h], dr, mul2(RE[h], di));
        RE[h] = nre; IM[h] = nim;
    }
}

__device__ __forceinline__ float laneWHT(float v, unsigned s0, unsigned s1, unsigned s2,
                                         unsigned s3, unsigned s4) {
    float t;
    t = __shfl_xor_sync(0xffffffffu, v, 1);  v = t + __uint_as_float(__float_as_uint(v) ^ s0);
    t = __shfl_xor_sync(0xffffffffu, v, 2);  v = t + __uint_as_float(__float_as_uint(v) ^ s1);
    t = __shfl_xor_sync(0xffffffffu, v, 4);  v = t + __uint_as_float(__float_as_uint(v) ^ s2);
    t = __shfl_xor_sync(0xffffffffu, v, 8);  v = t + __uint_as_float(__float_as_uint(v) ^ s3);
    t = __shfl_xor_sync(0xffffffffu, v, 16); v = t + __uint_as_float(__float_as_uint(v) ^ s4);
    return v;
}

// Frame: slot s = j0*0x003 ^ j1*0x006 ^ j2*0x00C ^ j3*0x018
//              ^ l0*0x001 ^ l1*0x020 ^ l2*0x040 ^ l3*0x080 ^ l4*0x100
__device__ __forceinline__ int slot_of(int ln, int j) {
    int s = 0;
    if (j & 1)  s ^= 0x003;
    if (j & 2)  s ^= 0x006;
    if (j & 4)  s ^= 0x00C;
    if (j & 8)  s ^= 0x018;
    if (ln & 1)  s ^= 0x001;
    if (ln & 2)  s ^= 0x020;
    if (ln & 4)  s ^= 0x040;
    if (ln & 8)  s ^= 0x080;
    if (ln & 16) s ^= 0x100;
    return s;
}

__global__ void __launch_bounds__(THREADS, 4)
qlayer_kernel(const float* __restrict__ x, const float* __restrict__ wts,
              float* __restrict__ out, int nsamp) {
    __shared__ float sw[81];
    __shared__ __align__(16) float s_m0[9][4];  // layer-0 matrices {m00r,m00i,m01r,m01i}
    __shared__ float s_y[2][9][2];              // layers 1,2 Ry coeffs {ct, st}
    __shared__ u64 sDR[2][8][32];               // diagonals D_A, D_B (cos), packed over j0
    __shared__ u64 sDI[2][8][32];               //                      (sin)
    __shared__ __align__(16) float4 s_init[WARPS_PER_BLOCK][9];  // per-warp init vectors

    const int tid = threadIdx.x;
    if (tid < 81) sw[tid] = wts[tid];
    __syncthreads();

    if (tid < 9) {
        const int qb = tid;
        const float phi = sw[qb * 3 + 0];
        const float th  = sw[qb * 3 + 1];
        const float om  = sw[qb * 3 + 2];
        float st, ct; sincosf(0.5f * th, &st, &ct);
        float sA, cA; sincosf(0.5f * (phi + om), &sA, &cA);
        float sB, cB; sincosf(0.5f * (phi - om), &sB, &cB);
        s_m0[qb][0] =  cA * ct;
        s_m0[qb][1] = -sA * ct;
        s_m0[qb][2] = -cB * st;
        s_m0[qb][3] = -sB * st;
    }
    if (tid < 18) {
        const int l = tid / 9 + 1, qb = tid % 9;
        float st, ct; sincosf(0.5f * sw[(l * 9 + qb) * 3 + 1], &st, &ct);
        s_y[l - 1][qb][0] = ct;
        s_y[l - 1][qb][1] = st;
    }
    {
        // D_A = Z(phi1)^{P1}; D_B = Z(om1)^{P1} * Z(phi2)^{P2}.
        // slot side1 (parity(row&s)=1) -> e^{+i a/2}, side0 -> e^{-i a/2}. (physical rows)
        constexpr int R1[9] = {0x1FF,0x1FE,0x1FC,0x1F8,0x1F0,0x1E0,0x1C0,0x180,0x0FF};
        constexpr int R2[9] = {0x0CC,0x066,0x133,0x198,0x0CF,0x060,0x13F,0x14C,0x099};
        const int h = tid >> 5, ln = tid & 31;
        const int sj[2] = { slot_of(ln, 2 * h), slot_of(ln, 2 * h + 1) };
        float thA[2] = {0.f, 0.f}, thB[2] = {0.f, 0.f};
        #pragma unroll
        for (int p = 0; p < 9; ++p) {
            const int q = 8 - p;
            const float f1 = sw[(9 + q) * 3 + 0];    // phi, layer 1
            const float o1 = sw[(9 + q) * 3 + 2];    // omega, layer 1
            const float f2 = sw[(18 + q) * 3 + 0];   // phi, layer 2
            #pragma unroll
            for (int e = 0; e < 2; ++e) {
                const int s = sj[e];
                const float g1 = (__popc(R1[p] & s) & 1) ? 0.5f : -0.5f;
                const float g2 = (__popc(R2[p] & s) & 1) ? 0.5f : -0.5f;
                thA[e] += g1 * f1;
                thB[e] += g1 * o1 + g2 * f2;
            }
        }
        float ca0, sa0, ca1, sa1, cb0, sb0, cb1, sb1;
        sincosf(thA[0], &sa0, &ca0); sincosf(thA[1], &sa1, &ca1);
        sincosf(thB[0], &sb0, &cb0); sincosf(thB[1], &sb1, &cb1);
        sDR[0][h][ln] = pk(ca0, ca1); sDI[0][h][ln] = pk(sa0, sa1);
        sDR[1][h][ln] = pk(cb0, cb1); sDI[1][h][ln] = pk(sb0, sb1);
    }
    __syncthreads();

    const int lane = tid & 31;
    const int warp = tid >> 5;
    const int b = blockIdx.x * WARPS_PER_BLOCK + warp;
    if (b >= nsamp) return;

    // --- per-qubit initial 2-vectors: lanes 0-8 compute, stage via smem ---
    if (lane < 9) {
        const float xv = x[b * 9 + lane];
        float sx, cx; sincosf(0.5f * xv, &sx, &cx);
        const float4 m = *reinterpret_cast<const float4*>(s_m0[lane]);
        float4 v;
        v.x =  m.x * cx + m.w * sx;
        v.y =  m.y * cx - m.z * sx;
        v.z = -m.z * cx - m.y * sx;
        v.w =  m.w * cx - m.x * sx;
        s_init[warp][lane] = v;
    }
    __syncwarp();
    float w0r[9], w0i[9], w1r[9], w1i[9];
    #pragma unroll
    for (int q = 0; q < 9; ++q) {
        const float4 v = s_init[warp][q];
        w0r[q] = v.x; w0i[q] = v.y; w1r[q] = v.z; w1i[q] = v.w;
    }

    const int l0 = lane & 1, l1 = (lane >> 1) & 1, l2 = (lane >> 2) & 1;
    const int l3 = (lane >> 3) & 1, l4 = (lane >> 4) & 1;

    // --- product state in frame coords ---
    // bit p factor: p0:w8[j0^l0] p1:w7[j0^j1] p2:w6[j1^j2] p3:w5[j2^j3] p4:w4[j3]
    //               p5:w3[l1] p6:w2[l2] p7:w1[l3] p8:w0[l4]   (w[q] = qubit q vector)
    float Br = l4 ? w1r[0] : w0r[0], Bi = l4 ? w1i[0] : w0i[0];
    cmul(Br, Bi, l3 ? w1r[1] : w0r[1], l3 ? w1i[1] : w0i[1]);
    cmul(Br, Bi, l2 ? w1r[2] : w0r[2], l2 ? w1i[2] : w0i[2]);
    cmul(Br, Bi, l1 ? w1r[3] : w0r[3], l1 ? w1i[3] : w0i[3]);

    u64 RE[8], IM[8];
    {
        float t1r[2], t1i[2];
        #pragma unroll
        for (int e3 = 0; e3 < 2; ++e3) {                 // j3
            t1r[e3] = Br; t1i[e3] = Bi;
            cmul(t1r[e3], t1i[e3], e3 ? w1r[4] : w0r[4], e3 ? w1i[4] : w0i[4]);
        }
        float t2r[4], t2i[4];
        #pragma unroll
        for (int t = 0; t < 4; ++t) {                    // (e2 = t&1, e3 = t>>1)
            const int e2 = t & 1, e3 = t >> 1;
            const int s3 = e2 ^ e3;
            t2r[t] = t1r[e3]; t2i[t] = t1i[e3];
            cmul(t2r[t], t2i[t], s3 ? w1r[5] : w0r[5], s3 ? w1i[5] : w0i[5]);
        }
        float t3r[8], t3i[8];
        #pragma unroll
        for (int h = 0; h < 8; ++h) {                    // h = j1 | j2<<1 | j3<<2
            const int e1 = h & 1, e2 = (h >> 1) & 1, e3 = h >> 2;
            const int s2 = e1 ^ e2;
            t3r[h] = t2r[e2 | (e3 << 1)]; t3i[h] = t2i[e2 | (e3 << 1)];
            cmul(t3r[h], t3i[h], s2 ? w1r[6] : w0r[6], s2 ? w1i[6] : w0i[6]);
        }
        // packed last two factors (over pack half = j0):
        const u64 W8R = pk(l0 ? w1r[8] : w0r[8], l0 ? w0r[8] : w1r[8]);
        const u64 W8I = pk(l0 ? w1i[8] : w0i[8], l0 ? w0i[8] : w1i[8]);
        const u64 W7R0 = pk(w0r[7], w1r[7]), W7I0 = pk(w0i[7], w1i[7]);
        const u64 W7R1 = pk(w1r[7], w0r[7]), W7I1 = pk(w1i[7], w0i[7]);
        #pragma unroll
        for (int h = 0; h < 8; ++h) {
            const u64 w7r = (h & 1) ? W7R1 : W7R0;
            const u64 w7i = (h & 1) ? W7I1 : W7I0;
            const u64 R0 = pk(t3r[h], t3r[h]);
            const u64 I0 = pk(t3i[h], t3i[h]);
            const u64 R1v = fma2(I0, neg64(w7i), mul2(R0, w7r));
            const u64 I1v = fma2(I0, w7r, mul2(R0, w7i));
            RE[h] = fma2(I1v, neg64(W8I), mul2(R1v, W8R));
            IM[h] = fma2(I1v, W8R, mul2(R1v, W8I));
        }
    }

    // --- D_A ---
    apply_diag(RE, IM, sDR[0], sDI[0], lane);

    // --- layer-1 Ry gates (frame coords; gate p -> qubit 8-p) ---
    gate_y<0x190, 0x1F0>(RE, IM, s_y[0][8][0], s_y[0][8][1], lane);  // p=0
    gate_y<0x001, 0x1E1>(RE, IM, s_y[0][7][0], s_y[0][7][1], lane);  // p=1
    gate_y<0x002, 0x1E2>(RE, IM, s_y[0][6][0], s_y[0][6][1], lane);  // p=2
    gate_y<0x004, 0x1E4>(RE, IM, s_y[0][5][0], s_y[0][5][1], lane);  // p=3
    gate_y<0x008, 0x1E8>(RE, IM, s_y[0][4][0], s_y[0][4][1], lane);  // p=4
    gate_y<0x03F, 0x1E0>(RE, IM, s_y[0][3][0], s_y[0][3][1], lane);  // p=5
    gate_y<0x060, 0x1C0>(RE, IM, s_y[0][2][0], s_y[0][2][1], lane);  // p=6
    gate_y<0x0C0, 0x180>(RE, IM, s_y[0][1][0], s_y[0][1][1], lane);  // p=7
    gate_y<0x180, 0x0F0>(RE, IM, s_y[0][0][0], s_y[0][0][1], lane);  // p=8

    // --- D_B ---
    apply_diag(RE, IM, sDR[1], sDI[1], lane);

    // --- layer-2 Ry gates ---  [Z(om2) dropped: pure phase before |.|^2]
    gate_y<0x16F, 0x0CA>(RE, IM, s_y[1][8][0], s_y[1][8][1], lane);  // p=0
    // p=1 and p=8 fused (both lane mask 0x1E; gates commute):
    gate_fused_1E(RE, IM, s_y[1][7][0], s_y[1][7][1],
                          s_y[1][0][0], s_y[1][0][1], lane);         // p=1 + p=8
    gate_y<0x192, 0x13A>(RE, IM, s_y[1][6][0], s_y[1][6][1], lane);  // p=2
    gate_y<0x005, 0x184>(RE, IM, s_y[1][5][0], s_y[1][5][1], lane);  // p=3
    gate_y<0x00A, 0x0D8>(RE, IM, s_y[1][4][0], s_y[1][4][1], lane);  // p=4
    gate_y<0x03B, 0x060>(RE, IM, s_y[1][3][0], s_y[1][3][1], lane);  // p=5
    gate_y<0x068, 0x130>(RE, IM, s_y[1][2][0], s_y[1][2][1], lane);  // p=6
    gate_y<0x0FF, 0x14A>(RE, IM, s_y[1][1][0], s_y[1][1][1], lane);  // p=7

    // --- probabilities, register-side WHT (over j) ---
    float prob[16];
    #pragma unroll
    for (int h = 0; h < 8; ++h) {
        const u64 P = fma2(IM[h], IM[h], mul2(RE[h], RE[h]));
        upk(P, prob[2 * h], prob[2 * h + 1]);
    }
    #pragma unroll
    for (int bb = 0; bb < 4; ++bb) {
        const int mk = 1 << bb;
        #pragma unroll
        for (int j = 0; j < 16; ++j) {
            if ((j & mk) != 0) continue;
            const float u = prob[j], v = prob[j | mk];
            prob[j] = u + v; prob[j | mk] = u - v;
        }
    }

    // --- lane-side WHTs; picks = M^T * ZM rows (coord Walsh indices) ---
    // w0:(A,0x15) w1:(D,0x0B) w2:(E,0x14) w3:(5,0x0F) w4:(2,0x19)
    // w5:(4,0x0B) w6:(F,0x1C) w7:(7,0x1F) w8:(E,0x07)
    const unsigned sg0 = (unsigned)( lane       & 1) << 31;
    const unsigned sg1 = (unsigned)((lane >> 1) & 1) << 31;
    const unsigned sg2 = (unsigned)((lane >> 2) & 1) << 31;
    const unsigned sg3 = (unsigned)((lane >> 3) & 1) << 31;
    const unsigned sg4 = (unsigned)((lane >> 4) & 1) << 31;
    const float SA = laneWHT(prob[0xA], sg0, sg1, sg2, sg3, sg4);
    const float SD = laneWHT(prob[0xD], sg0, sg1, sg2, sg3, sg4);
    const float SE = laneWHT(prob[0xE], sg0, sg1, sg2, sg3, sg4);
    const float S5 = laneWHT(prob[0x5], sg0, sg1, sg2, sg3, sg4);
    const float S2 = laneWHT(prob[0x2], sg0, sg1, sg2, sg3, sg4);
    const float S4 = laneWHT(prob[0x4], sg0, sg1, sg2, sg3, sg4);
    const float SF = laneWHT(prob[0xF], sg0, sg1, sg2, sg3, sg4);
    const float S7 = laneWHT(prob[0x7], sg0, sg1, sg2, sg3, sg4);

    const float r0 = __shfl_sync(0xffffffffu, SA, 0x15);
    const float r1 = __shfl_sync(0xffffffffu, SD, 0x0B);
    const float r2 = __shfl_sync(0xffffffffu, SE, 0x14);
    const float r3 = __shfl_sync(0xffffffffu, S5, 0x0F);
    const float r4 = __shfl_sync(0xffffffffu, S2, 0x19);
    const float r5 = __shfl_sync(0xffffffffu, S4, 0x0B);
    const float r6 = __shfl_sync(0xffffffffu, SF, 0x1C);
    const float r7 = __shfl_sync(0xffffffffu, S7, 0x1F);
    const float r8 = __shfl_sync(0xffffffffu, SE, 0x07);

    if (lane < 9) {
        float v = r0;
        if (lane == 1) v = r1;
        if (lane == 2) v = r2;
        if (lane == 3) v = r3;
        if (lane == 4) v = r4;
        if (lane == 5) v = r5;
        if (lane == 6) v = r6;
        if (lane == 7) v = r7;
        if (lane == 8) v = r8;
        out[b * 9 + lane] = v;
    }
}

extern "C" void kernel_launch(void* const* d_in, const int* in_sizes, int n_in,
                              void* d_out, int out_size) {
    const float* x   = (const float*)d_in[0];   // (32768, 9) float32
    const float* wts = (const float*)d_in[1];   // (3, 9, 3) float32
    float* out = (float*)d_out;                 // (32768, 9) float32
    const int nsamp = in_sizes[0] / 9;
    const int blocks = (nsamp + WARPS_PER_BLOCK - 1) / WARPS_PER_BLOCK;
    qlayer_kernel<<<blocks, THREADS>>>(x, wts, out, nsamp);
}

// round 13
// speedup vs baseline: 1.1742x; 1.0222x over previous
#include <cuda_runtime.h>
#include <cuda_bf16.h>

#define WARPS_PER_BLOCK 8
#define THREADS 256

typedef unsigned long long u64;

__host__ __device__ constexpr int msbbit(int v) { int b = 1; while (v >>= 1) b <<= 1; return b; }

__device__ __forceinline__ u64 pk(float lo, float hi) {
    u64 r; asm("mov.b64 %0, {%1, %2};" : "=l"(r) : "f"(lo), "f"(hi)); return r;
}
__device__ __forceinline__ u64 pkb(float v) {
    u64 r; asm("mov.b64 %0, {%1, %1};" : "=l"(r) : "f"(v)); return r;
}
__device__ __forceinline__ void upk(u64 v, float& lo, float& hi) {
    asm("mov.b64 {%0, %1}, %2;" : "=f"(lo), "=f"(hi) : "l"(v));
}
__device__ __forceinline__ u64 fma2(u64 a, u64 b, u64 c) {
    u64 r; asm("fma.rn.f32x2 %0, %1, %2, %3;" : "=l"(r) : "l"(a), "l"(b), "l"(c)); return r;
}
__device__ __forceinline__ u64 mul2(u64 a, u64 b) {
    u64 r; asm("mul.rn.f32x2 %0, %1, %2;" : "=l"(r) : "l"(a), "l"(b)); return r;
}
__device__ __forceinline__ u64 add2(u64 a, u64 b) {
    u64 r; asm("add.rn.f32x2 %0, %1, %2;" : "=l"(r) : "l"(a), "l"(b)); return r;
}
__device__ __forceinline__ u64 neg64(u64 v) { return v ^ 0x8000000080000000ULL; }

// packed complex multiply: (ar,ai) *= (br,bi), elementwise over the 2 samples
__device__ __forceinline__ void cmul2p(u64& ar, u64& ai, u64 br, u64 bi) {
    const u64 r = fma2(ai, neg64(bi), mul2(ar, br));
    const u64 i = fma2(ai, br, mul2(ar, bi));
    ar = r; ai = i;
}

// Real Ry gate on logical bit p, frame coords (lane 5b, reg 4b), 2 samples packed.
// MASK low4 = reg pairing mask, high5 = lane pairing mask; ROLE = side mask.
// side0 row = (ct, -st), side1 row = (ct, +st).
template<int MASK, int ROLE>
__device__ __forceinline__ void gate_y2(u64 (&RE)[16], u64 (&IM)[16],
                                        float ct, float st, int lane) {
    constexpr int ml = MASK & 0xF;
    constexpr int mw = (MASK >> 4) & 0x1F;
    const int lp = __popc((ROLE >> 4) & lane) & 1;
    const float base = lp ? st : -st;          // partner coeff for reg-parity 0
    const u64 C  = pkb(ct);
    const u64 S0 = pkb(base);
    const u64 S1 = neg64(S0);

    if constexpr (mw == 0) {
        constexpr int hb = msbbit(ml);
        #pragma unroll
        for (int j = 0; j < 16; ++j) {
            if ((j & hb) != 0) continue;
            const int k = j ^ ml;
            const u64 Sj = (__popc(ROLE & j) & 1) ? S1 : S0;
            const u64 Sk = (__popc(ROLE & k) & 1) ? S1 : S0;
            const u64 nrj = fma2(C, RE[j], mul2(Sj, RE[k]));
            const u64 nij = fma2(C, IM[j], mul2(Sj, IM[k]));
            const u64 nrk = fma2(C, RE[k], mul2(Sk, RE[j]));
            const u64 nik = fma2(C, IM[k], mul2(Sk, IM[j]));
            RE[j] = nrj; IM[j] = nij; RE[k] = nrk; IM[k] = nik;
        }
    } else if constexpr (ml == 0) {
        #pragma unroll
        for (int j = 0; j < 16; ++j) {
            const u64 pre = __shfl_xor_sync(0xffffffffu, RE[j], mw);
            const u64 pim = __shfl_xor_sync(0xffffffffu, IM[j], mw);
            const u64 Sj = (__popc(ROLE & j) & 1) ? S1 : S0;
            RE[j] = fma2(C, RE[j], mul2(Sj, pre));
            IM[j] = fma2(C, IM[j], mul2(Sj, pim));
        }
    } else {
        constexpr int hb = msbbit(ml);
        #pragma unroll
        for (int j = 0; j < 16; ++j) {
            if ((j & hb) != 0) continue;
            const int k = j ^ ml;
            const u64 prj = __shfl_xor_sync(0xffffffffu, RE[k], mw);
            const u64 pij = __shfl_xor_sync(0xffffffffu, IM[k], mw);
            const u64 prk = __shfl_xor_sync(0xffffffffu, RE[j], mw);
            const u64 pik = __shfl_xor_sync(0xffffffffu, IM[j], mw);
            const u64 Sj = (__popc(ROLE & j) & 1) ? S1 : S0;
            const u64 Sk = (__popc(ROLE & k) & 1) ? S1 : S0;
            RE[j] = fma2(C, RE[j], mul2(Sj, prj));
            IM[j] = fma2(C, IM[j], mul2(Sj, pij));
            RE[k] = fma2(C, RE[k], mul2(Sk, prk));
            IM[k] = fma2(C, IM[k], mul2(Sk, pik));
        }
    }
}

// Fused commuting L2 Ry pair sharing lane mask 0x1E:
//   A = (MASK 0x1E1, ROLE 0x065), B = (MASK 0x1E0, ROLE 0x095).
// out(u) = cAcB in(u) + cB sA(u) in(u^0x1E1) + cA sB(u) in(u^0x1E0)
//        + stA stB sgnAB(lane) in(u^0x001);  both reg-roles = 5, AB reg-role = 0.
__device__ __forceinline__ void gate_fused_1E2(u64 (&RE)[16], u64 (&IM)[16],
                                               float cA, float stA, float cB, float stB,
                                               int lane) {
    const int lpA  = __popc(0x06 & lane) & 1;
    const int lpB  = __popc(0x09 & lane) & 1;
    const int lpAB = __popc(0x0F & lane) & 1;
    const float cc     = cA * cB;
    const float baseA  = (lpA ? stA : -stA) * cB;
    const float baseB  = (lpB ? stB : -stB) * cA;
    const float baseAB = lpAB ? -(stA * stB) : (stA * stB);
    const u64 KC  = pkb(cc);
    const u64 KA0 = pkb(baseA), KA1 = neg64(KA0);
    const u64 KB0 = pkb(baseB), KB1 = neg64(KB0);
    const u64 KAB = pkb(baseAB);

    #pragma unroll
    for (int j = 0; j < 16; j += 2) {
        const int k = j + 1;
        const u64 srj = RE[j], sij = IM[j], srk = RE[k], sik = IM[k];
        const u64 prj = __shfl_xor_sync(0xffffffffu, srj, 0x1E);
        const u64 pij = __shfl_xor_sync(0xffffffffu, sij, 0x1E);
        const u64 prk = __shfl_xor_sync(0xffffffffu, srk, 0x1E);
        const u64 pik = __shfl_xor_sync(0xffffffffu, sik, 0x1E);
        const bool Tj = (__popc(5 & j) & 1) != 0;
        const u64 SAj = Tj ? KA1 : KA0, SAk = Tj ? KA0 : KA1;
        const u64 SBj = Tj ? KB1 : KB0, SBk = Tj ? KB0 : KB1;
        RE[j] = fma2(KC, srj, fma2(SAj, prk, fma2(SBj, prj, mul2(KAB, srk))));
        IM[j] = fma2(KC, sij, fma2(SAj, pik, fma2(SBj, pij, mul2(KAB, sik))));
        RE[k] = fma2(KC, srk, fma2(SAk, prj, fma2(SBk, prk, mul2(KAB, srj))));
        IM[k] = fma2(KC, sik, fma2(SAk, pij, fma2(SBk, pik, mul2(KAB, sij))));
    }
}

// state *= unit-modulus diagonal (scalar smem, broadcast into both samples)
__device__ __forceinline__ void apply_diag2(u64 (&RE)[16], u64 (&IM)[16],
                                            const float (*__restrict__ Dc)[32],
                                            const float (*__restrict__ Ds)[32], int lane) {
    #pragma unroll
    for (int j = 0; j < 16; ++j) {
        const u64 dr = pkb(Dc[j][lane]);
        const u64 di = pkb(Ds[j][lane]);
        const u64 nre = fma2(IM[j], neg64(di), mul2(RE[j], dr));
        const u64 nim = fma2(IM[j], dr, mul2(RE[j], di));
        RE[j] = nre; IM[j] = nim;
    }
}

__device__ __forceinline__ u64 laneWHT2(u64 v, u64 g0, u64 g1, u64 g2, u64 g3, u64 g4) {
    u64 t;
    t = __shfl_xor_sync(0xffffffffu, v, 1);  v = add2(t, v ^ g0);
    t = __shfl_xor_sync(0xffffffffu, v, 2);  v = add2(t, v ^ g1);
    t = __shfl_xor_sync(0xffffffffu, v, 4);  v = add2(t, v ^ g2);
    t = __shfl_xor_sync(0xffffffffu, v, 8);  v = add2(t, v ^ g3);
    t = __shfl_xor_sync(0xffffffffu, v, 16); v = add2(t, v ^ g4);
    return v;
}

// Frame: slot s = j0*0x003 ^ j1*0x006 ^ j2*0x00C ^ j3*0x018
//              ^ l0*0x001 ^ l1*0x020 ^ l2*0x040 ^ l3*0x080 ^ l4*0x100
__device__ __forceinline__ int slot_of(int ln, int j) {
    int s = 0;
    if (j & 1)  s ^= 0x003;
    if (j & 2)  s ^= 0x006;
    if (j & 4)  s ^= 0x00C;
    if (j & 8)  s ^= 0x018;
    if (ln & 1)  s ^= 0x001;
    if (ln & 2)  s ^= 0x020;
    if (ln & 4)  s ^= 0x040;
    if (ln & 8)  s ^= 0x080;
    if (ln & 16) s ^= 0x100;
    return s;
}

__global__ void __launch_bounds__(THREADS, 2)
qlayer_kernel(const float* __restrict__ x, const float* __restrict__ wts,
              float* __restrict__ out, int nsamp) {
    __shared__ float sw[81];
    __shared__ __align__(16) float s_m0[9][4];   // layer-0 matrices
    __shared__ float s_y[2][9][2];               // layers 1,2 Ry coeffs {ct, st}
    __shared__ float sDc[2][16][32];             // diagonals D_A, D_B: cos per (j,lane)
    __shared__ float sDs[2][16][32];             //                     sin
    __shared__ __align__(16) float4 s_init[WARPS_PER_BLOCK][2][9];  // per-warp, per-sample

    const int tid = threadIdx.x;
    if (tid < 81) sw[tid] = wts[tid];
    __syncthreads();

    if (tid < 9) {
        const int qb = tid;
        const float phi = sw[qb * 3 + 0];
        const float th  = sw[qb * 3 + 1];
        const float om  = sw[qb * 3 + 2];
        float st, ct; sincosf(0.5f * th, &st, &ct);
        float sA, cA; sincosf(0.5f * (phi + om), &sA, &cA);
        float sB, cB; sincosf(0.5f * (phi - om), &sB, &cB);
        s_m0[qb][0] =  cA * ct;
        s_m0[qb][1] = -sA * ct;
        s_m0[qb][2] = -cB * st;
        s_m0[qb][3] = -sB * st;
    }
    if (tid < 18) {
        const int l = tid / 9 + 1, qb = tid % 9;
        float st, ct; sincosf(0.5f * sw[(l * 9 + qb) * 3 + 1], &st, &ct);
        s_y[l - 1][qb][0] = ct;
        s_y[l - 1][qb][1] = st;
    }
    {
        // D_A = Z(phi1)^{P1}; D_B = Z(om1)^{P1} * Z(phi2)^{P2}.
        constexpr int R1[9] = {0x1FF,0x1FE,0x1FC,0x1F8,0x1F0,0x1E0,0x1C0,0x180,0x0FF};
        constexpr int R2[9] = {0x0CC,0x066,0x133,0x198,0x0CF,0x060,0x13F,0x14C,0x099};
        #pragma unroll
        for (int t = 0; t < 2; ++t) {
            const int idx = tid + t * 256;        // 512 (j,lane) pairs
            const int j = idx >> 5, ln = idx & 31;
            const int s = slot_of(ln, j);
            float thA = 0.f, thB = 0.f;
            #pragma unroll
            for (int p = 0; p < 9; ++p) {
                const int q = 8 - p;
                const float f1 = sw[(9 + q) * 3 + 0];
                const float o1 = sw[(9 + q) * 3 + 2];
                const float f2 = sw[(18 + q) * 3 + 0];
                const float g1 = (__popc(R1[p] & s) & 1) ? 0.5f : -0.5f;
                const float g2 = (__popc(R2[p] & s) & 1) ? 0.5f : -0.5f;
                thA += g1 * f1;
                thB += g1 * o1 + g2 * f2;
            }
            float ca, sa, cb, sb;
            sincosf(thA, &sa, &ca);
            sincosf(thB, &sb, &cb);
            sDc[0][j][ln] = ca; sDs[0][j][ln] = sa;
            sDc[1][j][ln] = cb; sDs[1][j][ln] = sb;
        }
    }
    __syncthreads();

    const int lane = tid & 31;
    const int warp = tid >> 5;
    const int pw = blockIdx.x * WARPS_PER_BLOCK + warp;   // sample-pair index
    const int b0 = 2 * pw;
    if (b0 >= nsamp) return;
    int b1 = b0 + 1; if (b1 >= nsamp) b1 = b0;

    // --- init vectors: lanes 0-8 do sample A, lanes 16-24 do sample B ---
    {
        int qb = -1, bb = 0;
        if (lane < 9) { qb = lane; bb = b0; }
        else if (lane >= 16 && lane < 25) { qb = lane - 16; bb = b1; }
        if (qb >= 0) {
            const float xv = x[bb * 9 + qb];
            float sx, cx; sincosf(0.5f * xv, &sx, &cx);
            const float4 m = *reinterpret_cast<const float4*>(s_m0[qb]);
            float4 v;
            v.x =  m.x * cx + m.w * sx;
            v.y =  m.y * cx - m.z * sx;
            v.z = -m.z * cx - m.y * sx;
            v.w =  m.w * cx - m.x * sx;
            s_init[warp][lane >> 4][qb] = v;
        }
    }
    __syncwarp();

    const int l0 = lane & 1, l1 = (lane >> 1) & 1, l2 = (lane >> 2) & 1;
    const int l3 = (lane >> 3) & 1, l4 = (lane >> 4) & 1;

    // --- packed product state (both samples at once) ---
    // factors: p0:w8[j0^l0] p1:w7[j0^j1] p2:w6[j1^j2] p3:w5[j2^j3] p4:w4[j3]
    //          p5:w3[l1] p6:w2[l2] p7:w1[l3] p8:w0[l4]
    u64 RE[16], IM[16];
    {
        auto loadq = [&](int q, u64& R0, u64& I0, u64& R1v, u64& I1v) {
            const float4 a = s_init[warp][0][q];
            const float4 c = s_init[warp][1][q];
            R0 = pk(a.x, c.x); I0 = pk(a.y, c.y);
            R1v = pk(a.z, c.z); I1v = pk(a.w, c.w);
        };
        u64 R0, I0, R1v, I1v;
        loadq(0, R0, I0, R1v, I1v);
        u64 Br = l4 ? R1v : R0, Bi = l4 ? I1v : I0;
        loadq(1, R0, I0, R1v, I1v);
        cmul2p(Br, Bi, l3 ? R1v : R0, l3 ? I1v : I0);
        loadq(2, R0, I0, R1v, I1v);
        cmul2p(Br, Bi, l2 ? R1v : R0, l2 ? I1v : I0);
        loadq(3, R0, I0, R1v, I1v);
        cmul2p(Br, Bi, l1 ? R1v : R0, l1 ? I1v : I0);

        u64 t1r[2], t1i[2];
        loadq(4, R0, I0, R1v, I1v);
        #pragma unroll
        for (int e3 = 0; e3 < 2; ++e3) {
            t1r[e3] = Br; t1i[e3] = Bi;
            cmul2p(t1r[e3], t1i[e3], e3 ? R1v : R0, e3 ? I1v : I0);
        }
        u64 t2r[4], t2i[4];
        loadq(5, R0, I0, R1v, I1v);
        #pragma unroll
        for (int t = 0; t < 4; ++t) {
            const int e2 = t & 1, e3 = t >> 1;
            const int s3 = e2 ^ e3;
            t2r[t] = t1r[e3]; t2i[t] = t1i[e3];
            cmul2p(t2r[t], t2i[t], s3 ? R1v : R0, s3 ? I1v : I0);
        }
        u64 t3r[8], t3i[8];
        loadq(6, R0, I0, R1v, I1v);
        #pragma unroll
        for (int h = 0; h < 8; ++h) {
            const int e1 = h & 1, e2 = (h >> 1) & 1;
            const int s2 = e1 ^ e2;
            t3r[h] = t2r[h >> 1]; t3i[h] = t2i[h >> 1];
            cmul2p(t3r[h], t3i[h], s2 ? R1v : R0, s2 ? I1v : I0);
        }
        u64 W7R0, W7I0, W7R1, W7I1;
        loadq(7, W7R0, W7I0, W7R1, W7I1);
        u64 W8R0, W8I0, W8R1, W8I1;
        loadq(8, W8R0, W8I0, W8R1, W8I1);
        const u64 F0R = l0 ? W8R1 : W8R0, F0I = l0 ? W8I1 : W8I0;   // j0 = 0
        const u64 F1R = l0 ? W8R0 : W8R1, F1I = l0 ? W8I0 : W8I1;   // j0 = 1
        #pragma unroll
        for (int j = 0; j < 16; ++j) {
            const int j0 = j & 1, e1 = (j >> 1) & 1;
            const int s1 = j0 ^ e1;
            RE[j] = t3r[j >> 1]; IM[j] = t3i[j >> 1];
            cmul2p(RE[j], IM[j], s1 ? W7R1 : W7R0, s1 ? W7I1 : W7I0);
            cmul2p(RE[j], IM[j], j0 ? F1R : F0R, j0 ? F1I : F0I);
        }
    }

    // --- D_A ---
    apply_diag2(RE, IM, sDc[0], sDs[0], lane);

    // --- layer-1 Ry gates ---
    gate_y2<0x190, 0x1F0>(RE, IM, s_y[0][8][0], s_y[0][8][1], lane);  // p=0
    gate_y2<0x001, 0x1E1>(RE, IM, s_y[0][7][0], s_y[0][7][1], lane);  // p=1
    gate_y2<0x002, 0x1E2>(RE, IM, s_y[0][6][0], s_y[0][6][1], lane);  // p=2
    gate_y2<0x004, 0x1E4>(RE, IM, s_y[0][5][0], s_y[0][5][1], lane);  // p=3
    gate_y2<0x008, 0x1E8>(RE, IM, s_y[0][4][0], s_y[0][4][1], lane);  // p=4
    gate_y2<0x03F, 0x1E0>(RE, IM, s_y[0][3][0], s_y[0][3][1], lane);  // p=5
    gate_y2<0x060, 0x1C0>(RE, IM, s_y[0][2][0], s_y[0][2][1], lane);  // p=6
    gate_y2<0x0C0, 0x180>(RE, IM, s_y[0][1][0], s_y[0][1][1], lane);  // p=7
    gate_y2<0x180, 0x0F0>(RE, IM, s_y[0][0][0], s_y[0][0][1], lane);  // p=8

    // --- D_B ---
    apply_diag2(RE, IM, sDc[1], sDs[1], lane);

    // --- layer-2 Ry gates ---  [Z(om2) dropped: pure phase before |.|^2]
    gate_y2<0x16F, 0x0CA>(RE, IM, s_y[1][8][0], s_y[1][8][1], lane);  // p=0
    gate_fused_1E2(RE, IM, s_y[1][7][0], s_y[1][7][1],
                           s_y[1][0][0], s_y[1][0][1], lane);         // p=1 + p=8
    gate_y2<0x192, 0x13A>(RE, IM, s_y[1][6][0], s_y[1][6][1], lane);  // p=2
    gate_y2<0x005, 0x184>(RE, IM, s_y[1][5][0], s_y[1][5][1], lane);  // p=3
    gate_y2<0x00A, 0x0D8>(RE, IM, s_y[1][4][0], s_y[1][4][1], lane);  // p=4
    gate_y2<0x03B, 0x060>(RE, IM, s_y[1][3][0], s_y[1][3][1], lane);  // p=5
    gate_y2<0x068, 0x130>(RE, IM, s_y[1][2][0], s_y[1][2][1], lane);  // p=6
    gate_y2<0x0FF, 0x14A>(RE, IM, s_y[1][1][0], s_y[1][1][1], lane);  // p=7

    // --- probabilities (packed over samples), register-side WHT over j ---
    u64 prob[16];
    #pragma unroll
    for (int j = 0; j < 16; ++j)
        prob[j] = fma2(IM[j], IM[j], mul2(RE[j], RE[j]));
    #pragma unroll
    for (int bb = 0; bb < 4; ++bb) {
        const int mk = 1 << bb;
        #pragma unroll
        for (int j = 0; j < 16; ++j) {
            if ((j & mk) != 0) continue;
            const u64 u = prob[j], v = prob[j | mk];
            prob[j] = add2(u, v);
            prob[j | mk] = add2(u, neg64(v));
        }
    }

    // --- lane-side WHTs; picks = coord Walsh indices (unchanged) ---
    const u64 g0 = (lane & 1)        ? 0x8000000080000000ULL : 0ULL;
    const u64 g1 = ((lane >> 1) & 1) ? 0x8000000080000000ULL : 0ULL;
    const u64 g2 = ((lane >> 2) & 1) ? 0x8000000080000000ULL : 0ULL;
    const u64 g3 = ((lane >> 3) & 1) ? 0x8000000080000000ULL : 0ULL;
    const u64 g4 = ((lane >> 4) & 1) ? 0x8000000080000000ULL : 0ULL;
    const u64 SA = laneWHT2(prob[0xA], g0, g1, g2, g3, g4);
    const u64 SD = laneWHT2(prob[0xD], g0, g1, g2, g3, g4);
    const u64 SE = laneWHT2(prob[0xE], g0, g1, g2, g3, g4);
    const u64 S5 = laneWHT2(prob[0x5], g0, g1, g2, g3, g4);
    const u64 S2 = laneWHT2(prob[0x2], g0, g1, g2, g3, g4);
    const u64 S4 = laneWHT2(prob[0x4], g0, g1, g2, g3, g4);
    const u64 SF = laneWHT2(prob[0xF], g0, g1, g2, g3, g4);
    const u64 S7 = laneWHT2(prob[0x7], g0, g1, g2, g3, g4);

    const u64 r0 = __shfl_sync(0xffffffffu, SA, 0x15);
    const u64 r1 = __shfl_sync(0xffffffffu, SD, 0x0B);
    const u64 r2 = __shfl_sync(0xffffffffu, SE, 0x14);
    const u64 r3 = __shfl_sync(0xffffffffu, S5, 0x0F);
    const u64 r4 = __shfl_sync(0xffffffffu, S2, 0x19);
    const u64 r5 = __shfl_sync(0xffffffffu, S4, 0x0B);
    const u64 r6 = __shfl_sync(0xffffffffu, SF, 0x1C);
    const u64 r7 = __shfl_sync(0xffffffffu, S7, 0x1F);
    const u64 r8 = __shfl_sync(0xffffffffu, SE, 0x07);

    if (lane < 9) {
        u64 v = r0;
        if (lane == 1) v = r1;
        if (lane == 2) v = r2;
        if (lane == 3) v = r3;
        if (lane == 4) v = r4;
        if (lane == 5) v = r5;
        if (lane == 6) v = r6;
        if (lane == 7) v = r7;
        if (lane == 8) v = r8;
        float lo, hi; upk(v, lo, hi);
        out[b0 * 9 + lane] = lo;
        out[b1 * 9 + lane] = hi;
    }
}

extern "C" void kernel_launch(void* const* d_in, const int* in_sizes, int n_in,
                              void* d_out, int out_size) {
    const float* x   = (const float*)d_in[0];   // (32768, 9) float32
    const float* wts = (const float*)d_in[1];   // (3, 9, 3) float32
    float* out = (float*)d_out;                 // (32768, 9) float32
    const int nsamp = in_sizes[0] / 9;
    const int npairs = (nsamp + 1) / 2;
    const int blocks = (npairs + WARPS_PER_BLOCK - 1) / WARPS_PER_BLOCK;
    qlayer_kernel<<<blocks, THREADS>>>(x, wts, out, nsamp);
}